// round 15
// baseline (speedup 1.0000x reference)
#include <cuda_runtime.h>
#include <cuda_bf16.h>

// Problem constants
#define Bv   64
#define Sv   512
#define Ev   1024
#define Hv   16
#define Dv   64
#define Mtot (Bv*Sv)   // 32768

// ---------------------------------------------------------------------------
// Scratch (__device__ globals; no allocation allowed).
// NOTE: reference these ONLY from device code (host-passed args bind the
// host-side shadow via GB300 ATS and silently corrupt).
//
// "hl" arrays are word-interleaved hi/lo: 32-bit word 2w = bf16x2 hi-pair for
// elements (2w, 2w+1), word 2w+1 = lo-pair. Word index == element index.
// ---------------------------------------------------------------------------
__device__ __nv_bfloat16 g_Xhl [2*Mtot*Ev];   // X split-interleaved, [M,K]
__device__ __nv_bfloat16 g_Whl [2*4*Ev*Ev];   // W^T split-interleaved, [N,K] x4
__device__ __nv_bfloat16 g_Qhi [Mtot*Ev];     // [B,H,S,D] bf16 hi/lo (flash fmt)
__device__ __nv_bfloat16 g_Qlo [Mtot*Ev];
__device__ __nv_bfloat16 g_Khi [Mtot*Ev];
__device__ __nv_bfloat16 g_Klo [Mtot*Ev];
__device__ __nv_bfloat16 g_Vthi[Mtot*Ev];     // V transposed: [B,H,D,S]
__device__ __nv_bfloat16 g_Vtlo[Mtot*Ev];
__device__ __nv_bfloat16 g_AOhl[2*Mtot*Ev];   // attention out split-interleaved

// ---------------------------------------------------------------------------
// PTX helpers (Ampere-era: legal on plain sm_103 target)
// ---------------------------------------------------------------------------
__device__ __forceinline__ unsigned smem_u32(const void* p) {
    unsigned a;
    asm("{ .reg .u64 t; cvta.to.shared.u64 t, %1; cvt.u32.u64 %0, t; }" : "=r"(a) : "l"(p));
    return a;
}
__device__ __forceinline__ void cp_async16(unsigned s, const void* g) {
    asm volatile("cp.async.cg.shared.global [%0], [%1], 16;" :: "r"(s), "l"(g));
}
#define CP_COMMIT() asm volatile("cp.async.commit_group;" ::: "memory")
#define CP_WAIT(n)  asm volatile("cp.async.wait_group %0;" :: "n"(n) : "memory")

#define MMA_BF16(c, a, b) \
    asm volatile("mma.sync.aligned.m16n8k16.row.col.f32.bf16.bf16.f32 " \
        "{%0,%1,%2,%3}, {%4,%5,%6,%7}, {%8,%9}, {%0,%1,%2,%3};" \
        : "+f"((c)[0]), "+f"((c)[1]), "+f"((c)[2]), "+f"((c)[3]) \
        : "r"((a)[0]), "r"((a)[1]), "r"((a)[2]), "r"((a)[3]), \
          "r"((b)[0]), "r"((b)[1]))

// hi/lo bf16 split of a float pair, packed as bf16x2 words (low = first elem)
__device__ __forceinline__ void split2(float x0, float x1, unsigned& h, unsigned& l) {
    __nv_bfloat16 h0 = __float2bfloat16(x0), h1 = __float2bfloat16(x1);
    __nv_bfloat162 hh(h0, h1);
    __nv_bfloat162 ll(__float2bfloat16(x0 - __bfloat162float(h0)),
                      __float2bfloat16(x1 - __bfloat162float(h1)));
    h = *(unsigned*)&hh;
    l = *(unsigned*)&ll;
}

// ---------------------------------------------------------------------------
// Split / transpose precompute kernels (write device globals directly!)
// ---------------------------------------------------------------------------
__global__ __launch_bounds__(256)
void split_x(const float* __restrict__ in, int n)
{
    unsigned* ow = (unsigned*)g_Xhl;
    for (long long i = ((long long)blockIdx.x * 256 + threadIdx.x) * 4; i < n;
         i += (long long)gridDim.x * 1024) {
        float4 v = *(const float4*)(in + i);
        unsigned h0, l0, h1, l1;
        split2(v.x, v.y, h0, l0);
        split2(v.z, v.w, h1, l1);
        uint4 o = make_uint4(h0, l0, h1, l1);
        *(uint4*)(ow + i) = o;              // word offset == element offset
    }
}

// W [K,N] fp32 -> W^T [N,K] split-interleaved. grid (32,32,4), block 256
__global__ __launch_bounds__(256)
void split_w(const float* __restrict__ Wq, const float* __restrict__ Wk,
             const float* __restrict__ Wv, const float* __restrict__ Wo)
{
    __shared__ float t[32][33];
    const float* W = (blockIdx.z == 0) ? Wq : (blockIdx.z == 1) ? Wk
                     : (blockIdx.z == 2) ? Wv : Wo;
    const int n0 = blockIdx.x * 32, k0 = blockIdx.y * 32;
    const int tx = threadIdx.x & 31, ty = threadIdx.x >> 5;
    #pragma unroll
    for (int i = 0; i < 4; i++)
        t[ty + i*8][tx] = W[(size_t)(k0 + ty + i*8) * Ev + n0 + tx];
    __syncthreads();
    unsigned* ow = (unsigned*)g_Whl;
    const size_t zo = (size_t)blockIdx.z * Ev * Ev;
    const int kp = threadIdx.x & 15;       // k-pair 0..15
    const int nn = threadIdx.x >> 4;       // 0..15
    #pragma unroll
    for (int j = 0; j < 2; ++j) {
        int n = nn + j * 16;
        unsigned hw, lw;
        split2(t[2*kp][n], t[2*kp + 1][n], hw, lw);
        size_t w = zo + (size_t)(n0 + n) * Ev + k0 + 2*kp;
        *(uint2*)(ow + w) = make_uint2(hw, lw);
    }
}

// ---------------------------------------------------------------------------
// HMMA GEMM mainloop v2: hi/lo word-interleaved tiles, LDS.64 fragment loads.
// CTA tile 128x128, BK=32, 8 warps (64x32 warp tiles).
// Smem rows: 32 data words (32 k-values hi/lo interleaved) padded to 40 words
// (160 B). Row stride 40 = 8 mod 32 -> each 16-lane LDS.64 phase covers banks
// {0-7}{8-15}{16-23}{24-31}: conflict-free. Fragment values land in the SAME
// registers as the validated scalar version (one LDS.64 = (hi_i, lo_i)).
// ---------------------------------------------------------------------------
#define KITERS 32         // 1024 / 32
#define TILEB  20480      // 128 rows * 160 bytes
#define BUFSZ  40960      // 2 tiles (A_hl, B_hl)
#define RW     40         // words per smem row

__device__ __forceinline__ void hmma_gemm_tile(
    const unsigned* __restrict__ Aw, const unsigned* __restrict__ Bw,
    char* smp, unsigned sbase, float acc[4][4][4])
{
    const int tid  = threadIdx.x;
    const int lane = tid & 31;
    const int wid  = tid >> 5;
    const int wm   = (wid & 1) * 64;
    const int wn   = (wid >> 1) * 32;
    const int fr   = lane >> 2;     // 0..7
    const int ft   = lane & 3;      // 0..3

    // fill: 2 tiles x (128 rows x 8 chunks of 16B), 8 cp.async per thread
    auto fill = [&](int buf, int k0w) {
        const unsigned boff = sbase + buf * BUFSZ;
        #pragma unroll
        for (int it = 0; it < 8; ++it) {
            const int t = it >> 2;                 // 0 = A, 1 = B
            int e = tid + (it & 3) * 256;          // 0..1023
            int r = e >> 3, c = e & 7;
            const unsigned* g = (t == 0 ? Aw : Bw) + (size_t)r * Ev + k0w + c * 4;
            cp_async16(boff + t * TILEB + r * 160 + c * 16, g);
        }
    };

    fill(0, 0); CP_COMMIT();

    for (int cIt = 0; cIt < KITERS; ++cIt) {
        const int buf = cIt & 1;
        if (cIt + 1 < KITERS) { fill(buf ^ 1, (cIt + 1) * 32); CP_COMMIT(); CP_WAIT(1); }
        else                  { CP_WAIT(0); }
        __syncthreads();

        const unsigned* SA = (const unsigned*)(smp + buf * BUFSZ);
        const unsigned* SB = (const unsigned*)(smp + buf * BUFSZ + TILEB);

        #pragma unroll
        for (int ks2 = 0; ks2 < 16; ks2 += 8) {
            unsigned bh[4][2], bl[4][2];
            #pragma unroll
            for (int na = 0; na < 4; ++na) {
                int w = (wn + na * 8 + fr) * RW + 2 * (ks2 + ft);
                uint2 b0 = *(const uint2*)(SB + w);
                uint2 b1 = *(const uint2*)(SB + w + 8);
                bh[na][0] = b0.x;  bl[na][0] = b0.y;
                bh[na][1] = b1.x;  bl[na][1] = b1.y;
            }
            #pragma unroll
            for (int ma = 0; ma < 4; ++ma) {
                int w = (wm + ma * 16 + fr) * RW + 2 * (ks2 + ft);
                uint2 a0 = *(const uint2*)(SA + w);
                uint2 a2 = *(const uint2*)(SA + w + 8);
                uint2 a1 = *(const uint2*)(SA + w + 8 * RW);
                uint2 a3 = *(const uint2*)(SA + w + 8 * RW + 8);
                unsigned ah[4] = {a0.x, a1.x, a2.x, a3.x};
                unsigned al[4] = {a0.y, a1.y, a2.y, a3.y};
                #pragma unroll
                for (int na = 0; na < 4; ++na) {
                    MMA_BF16(acc[ma][na], ah, bh[na]);
                    MMA_BF16(acc[ma][na], ah, bl[na]);
                    MMA_BF16(acc[ma][na], al, bh[na]);
                }
            }
        }
        __syncthreads();
    }
}

// ---------------------------------------------------------------------------
// QKV: X @ {Wq,Wk,Wv}. Epilogue writes bf16 hi/lo (flash format, unchanged):
//   z=0 -> Q [B,H,S,D], z=1 -> K [B,H,S,D], z=2 -> V^T [B,H,D,S]
// grid (8, 256, 3)
// ---------------------------------------------------------------------------
__global__ __launch_bounds__(256, 2)
void qkv_mma()
{
    extern __shared__ char dsm[];
    unsigned raw   = smem_u32(dsm);
    unsigned sbase = (raw + 127) & ~127u;
    char* smp = dsm + (sbase - raw);

    const int z    = blockIdx.z;
    const int row0 = blockIdx.y * 128;
    const int col0 = blockIdx.x * 128;

    float acc[4][4][4] = {};
    hmma_gemm_tile((const unsigned*)g_Xhl + (size_t)row0 * Ev,
                   (const unsigned*)g_Whl + (size_t)z * Ev * Ev + (size_t)col0 * Ev,
                   smp, sbase, acc);

    const int lane = threadIdx.x & 31, wid = threadIdx.x >> 5;
    const int wm = (wid & 1) * 64, wn = (wid >> 1) * 32;
    const int grp = lane >> 2, tig = lane & 3;

    if (z < 2) {
        __nv_bfloat16* Ohi = (z == 0) ? g_Qhi : g_Khi;
        __nv_bfloat16* Olo = (z == 0) ? g_Qlo : g_Klo;
        #pragma unroll
        for (int ma = 0; ma < 4; ++ma) {
            #pragma unroll
            for (int na = 0; na < 4; ++na) {
                int n = col0 + wn + na * 8 + tig * 2;
                int h = n >> 6, d = n & 63;
                #pragma unroll
                for (int half = 0; half < 2; ++half) {
                    int m = row0 + wm + ma * 16 + grp + half * 8;
                    int b = m >> 9, s = m & 511;
                    size_t off = ((size_t)(b * Hv + h) * Sv + s) * Dv + d;
                    unsigned hw, lw;
                    split2(acc[ma][na][half*2], acc[ma][na][half*2+1], hw, lw);
                    *(unsigned*)(Ohi + off) = hw;
                    *(unsigned*)(Olo + off) = lw;
                }
            }
        }
    } else {
        #pragma unroll
        for (int ma = 0; ma < 4; ++ma) {
            #pragma unroll
            for (int na = 0; na < 4; ++na) {
                int n = col0 + wn + na * 8 + tig * 2;
                int h = n >> 6, d = n & 63;
                #pragma unroll
                for (int half = 0; half < 2; ++half) {
                    int m = row0 + wm + ma * 16 + grp + half * 8;
                    int b = m >> 9, s = m & 511;
                    #pragma unroll
                    for (int e = 0; e < 2; ++e) {
                        float x = acc[ma][na][half*2 + e];
                        __nv_bfloat16 hh = __float2bfloat16(x);
                        __nv_bfloat16 ll = __float2bfloat16(x - __bfloat162float(hh));
                        size_t off = ((size_t)(b * Hv + h) * Dv + d + e) * Sv + s;
                        g_Vthi[off] = hh;
                        g_Vtlo[off] = ll;
                    }
                }
            }
        }
    }
}

// ---------------------------------------------------------------------------
// Output projection: AO @ Wo + bo -> out.  grid (8, 256)
// ---------------------------------------------------------------------------
__global__ __launch_bounds__(256, 2)
void out_mma(const float* __restrict__ bo, float* __restrict__ Cout)
{
    extern __shared__ char dsm[];
    unsigned raw   = smem_u32(dsm);
    unsigned sbase = (raw + 127) & ~127u;
    char* smp = dsm + (sbase - raw);

    const int row0 = blockIdx.y * 128;
    const int col0 = blockIdx.x * 128;

    float acc[4][4][4] = {};
    hmma_gemm_tile((const unsigned*)g_AOhl + (size_t)row0 * Ev,
                   (const unsigned*)g_Whl + (size_t)3 * Ev * Ev + (size_t)col0 * Ev,
                   smp, sbase, acc);

    const int lane = threadIdx.x & 31, wid = threadIdx.x >> 5;
    const int wm = (wid & 1) * 64, wn = (wid >> 1) * 32;
    const int grp = lane >> 2, tig = lane & 3;

    #pragma unroll
    for (int ma = 0; ma < 4; ++ma) {
        #pragma unroll
        for (int na = 0; na < 4; ++na) {
            int n = col0 + wn + na * 8 + tig * 2;
            float2 bia = *(const float2*)(bo + n);
            #pragma unroll
            for (int half = 0; half < 2; ++half) {
                int m = row0 + wm + ma * 16 + grp + half * 8;
                float* dst = Cout + (size_t)m * Ev + n;
                *(float2*)dst = make_float2(acc[ma][na][half*2]   + bia.x,
                                            acc[ma][na][half*2+1] + bia.y);
            }
        }
    }
}

// ---------------------------------------------------------------------------
// Tensorized flash attention (causal, NO 1/sqrt(d) scale). Unchanged from R14
// except the AO epilogue writes the word-interleaved hi/lo format.
// ---------------------------------------------------------------------------
#define TROW 36                 // words per smem row
#define TSZ  (64 * TROW * 4)    // 9216 B per tile
#define FBUF (4 * TSZ)          // 36864 B per buffer (Kh, Kl, Vth, Vtl)

__global__ __launch_bounds__(256, 2)
void flash_attn()
{
    extern __shared__ char dsm[];
    unsigned raw   = smem_u32(dsm);
    unsigned sbase = (raw + 127) & ~127u;
    char* smp = dsm + (sbase - raw);

    const int qt = blockIdx.x;          // 0..3 (128-row q tiles)
    const int h  = blockIdx.y;
    const int b  = blockIdx.z;
    const int q0 = qt * 128;

    const int tid  = threadIdx.x;
    const int lane = tid & 31;
    const int wid  = tid >> 5;
    const int grp  = lane >> 2;         // 0..7
    const int ft   = lane & 3;          // 0..3
    const int wm   = wid * 16;

    const long long bh = (long long)b * Hv + h;

    // Q fragments (persistent in registers): rows q0+wm .. +15, 32 words/row
    const unsigned* Qhw = (const unsigned*)g_Qhi + (bh * Sv + q0 + wm) * 32;
    const unsigned* Qlw = (const unsigned*)g_Qlo + (bh * Sv + q0 + wm) * 32;
    unsigned qh[4][4], ql[4][4];
    #pragma unroll
    for (int kc = 0; kc < 4; ++kc) {
        int w0 = grp * 32 + kc * 8 + ft;
        qh[kc][0] = Qhw[w0];       qh[kc][1] = Qhw[w0 + 256];
        qh[kc][2] = Qhw[w0 + 4];   qh[kc][3] = Qhw[w0 + 260];
        ql[kc][0] = Qlw[w0];       ql[kc][1] = Qlw[w0 + 256];
        ql[kc][2] = Qlw[w0 + 4];   ql[kc][3] = Qlw[w0 + 260];
    }

    const __nv_bfloat16* Kh  = g_Khi  + bh * Sv * Dv;
    const __nv_bfloat16* Kl  = g_Klo  + bh * Sv * Dv;
    const __nv_bfloat16* Vth = g_Vthi + bh * Dv * Sv;
    const __nv_bfloat16* Vtl = g_Vtlo + bh * Dv * Sv;

    float O[8][4] = {};
    float m0 = -1e30f, m1 = -1e30f, l0 = 0.f, l1 = 0.f;

    const int kbmax = 2 * (qt + 1);

    auto fill = [&](int buf, int kb) {
        const unsigned boff = sbase + buf * FBUF;
        #pragma unroll
        for (int it = 0; it < 8; ++it) {
            const int t = it >> 1;
            int e = tid + (it & 1) * 256;     // 0..511
            int r = e >> 3, c = e & 7;
            const __nv_bfloat16* g;
            if      (t == 0) g = Kh  + (size_t)(kb * 64 + r) * Dv + c * 8;
            else if (t == 1) g = Kl  + (size_t)(kb * 64 + r) * Dv + c * 8;
            else if (t == 2) g = Vth + (size_t)r * Sv + kb * 64 + c * 8;
            else             g = Vtl + (size_t)r * Sv + kb * 64 + c * 8;
            cp_async16(boff + t * TSZ + r * 144 + c * 16, g);
        }
    };

    fill(0, 0); CP_COMMIT();

    for (int kb = 0; kb < kbmax; ++kb) {
        const int buf = kb & 1;
        if (kb + 1 < kbmax) { fill(buf ^ 1, kb + 1); CP_COMMIT(); CP_WAIT(1); }
        else                { CP_WAIT(0); }
        __syncthreads();

        const unsigned* SK_h = (const unsigned*)(smp + buf * FBUF);
        const unsigned* SK_l = (const unsigned*)(smp + buf * FBUF + TSZ);
        const unsigned* SV_h = (const unsigned*)(smp + buf * FBUF + 2 * TSZ);
        const unsigned* SV_l = (const unsigned*)(smp + buf * FBUF + 3 * TSZ);

        // S = Q @ K^T (16x64 per warp), 3-term split
        float sacc[8][4] = {};
        #pragma unroll
        for (int kc = 0; kc < 4; ++kc) {
            unsigned bhf[8][2], blf[8][2];
            #pragma unroll
            for (int nt = 0; nt < 8; ++nt) {
                int w = (nt * 8 + grp) * TROW + kc * 8 + ft;
                bhf[nt][0] = SK_h[w];  bhf[nt][1] = SK_h[w + 4];
                blf[nt][0] = SK_l[w];  blf[nt][1] = SK_l[w + 4];
            }
            #pragma unroll
            for (int nt = 0; nt < 8; ++nt) {
                MMA_BF16(sacc[nt], qh[kc], bhf[nt]);
                MMA_BF16(sacc[nt], qh[kc], blf[nt]);
                MMA_BF16(sacc[nt], ql[kc], bhf[nt]);
            }
        }

        // causal mask (only the last two key blocks can cross the diagonal)
        if (kb >= kbmax - 2) {
            int r0 = q0 + wm + grp, r1 = r0 + 8;
            #pragma unroll
            for (int nt = 0; nt < 8; ++nt) {
                int c0 = kb * 64 + nt * 8 + 2 * ft;
                if (c0     > r0) sacc[nt][0] = -1e30f;
                if (c0 + 1 > r0) sacc[nt][1] = -1e30f;
                if (c0     > r1) sacc[nt][2] = -1e30f;
                if (c0 + 1 > r1) sacc[nt][3] = -1e30f;
            }
        }

        // online softmax in registers (rows grp / grp+8; quad holds full row)
        float mx0 = -1e30f, mx1 = -1e30f;
        #pragma unroll
        for (int nt = 0; nt < 8; ++nt) {
            mx0 = fmaxf(mx0, fmaxf(sacc[nt][0], sacc[nt][1]));
            mx1 = fmaxf(mx1, fmaxf(sacc[nt][2], sacc[nt][3]));
        }
        mx0 = fmaxf(mx0, __shfl_xor_sync(0xffffffffu, mx0, 1));
        mx0 = fmaxf(mx0, __shfl_xor_sync(0xffffffffu, mx0, 2));
        mx1 = fmaxf(mx1, __shfl_xor_sync(0xffffffffu, mx1, 1));
        mx1 = fmaxf(mx1, __shfl_xor_sync(0xffffffffu, mx1, 2));

        float mn0 = fmaxf(m0, mx0), mn1 = fmaxf(m1, mx1);
        float al0 = __expf(m0 - mn0), al1 = __expf(m1 - mn1);
        float ps0 = 0.f, ps1 = 0.f;
        #pragma unroll
        for (int nt = 0; nt < 8; ++nt) {
            sacc[nt][0] = __expf(sacc[nt][0] - mn0);
            sacc[nt][1] = __expf(sacc[nt][1] - mn0);
            sacc[nt][2] = __expf(sacc[nt][2] - mn1);
            sacc[nt][3] = __expf(sacc[nt][3] - mn1);
            ps0 += sacc[nt][0] + sacc[nt][1];
            ps1 += sacc[nt][2] + sacc[nt][3];
        }
        ps0 += __shfl_xor_sync(0xffffffffu, ps0, 1);
        ps0 += __shfl_xor_sync(0xffffffffu, ps0, 2);
        ps1 += __shfl_xor_sync(0xffffffffu, ps1, 1);
        ps1 += __shfl_xor_sync(0xffffffffu, ps1, 2);
        l0 = l0 * al0 + ps0;  l1 = l1 * al1 + ps1;
        m0 = mn0;             m1 = mn1;
        #pragma unroll
        for (int nt = 0; nt < 8; ++nt) {
            O[nt][0] *= al0;  O[nt][1] *= al0;
            O[nt][2] *= al1;  O[nt][3] *= al1;
        }

        // repack P (C layout -> A fragments, hi/lo split), lane-local
        unsigned ph[4][4], pl[4][4];
        #pragma unroll
        for (int kc = 0; kc < 4; ++kc) {
            split2(sacc[2*kc][0],   sacc[2*kc][1],   ph[kc][0], pl[kc][0]);
            split2(sacc[2*kc][2],   sacc[2*kc][3],   ph[kc][1], pl[kc][1]);
            split2(sacc[2*kc+1][0], sacc[2*kc+1][1], ph[kc][2], pl[kc][2]);
            split2(sacc[2*kc+1][2], sacc[2*kc+1][3], ph[kc][3], pl[kc][3]);
        }

        // O += P @ V  (V^T tile in smem is exactly B-fragment layout)
        #pragma unroll
        for (int kc = 0; kc < 4; ++kc) {
            unsigned vh[8][2], vl[8][2];
            #pragma unroll
            for (int nt = 0; nt < 8; ++nt) {
                int w = (nt * 8 + grp) * TROW + kc * 8 + ft;
                vh[nt][0] = SV_h[w];  vh[nt][1] = SV_h[w + 4];
                vl[nt][0] = SV_l[w];  vl[nt][1] = SV_l[w + 4];
            }
            #pragma unroll
            for (int nt = 0; nt < 8; ++nt) {
                MMA_BF16(O[nt], ph[kc], vh[nt]);
                MMA_BF16(O[nt], ph[kc], vl[nt]);
                MMA_BF16(O[nt], pl[kc], vh[nt]);
            }
        }
        __syncthreads();
    }

    // normalize + write AO (word-interleaved hi/lo) into [B,S,E]
    unsigned* AOw = (unsigned*)g_AOhl;
    float inv0 = 1.f / l0, inv1 = 1.f / l1;
    int r0 = q0 + wm + grp, r1 = r0 + 8;
    #pragma unroll
    for (int nt = 0; nt < 8; ++nt) {
        int d = nt * 8 + 2 * ft;
        size_t off0 = ((size_t)b * Sv + r0) * Ev + h * 64 + d;
        size_t off1 = ((size_t)b * Sv + r1) * Ev + h * 64 + d;
        unsigned hw, lw;
        split2(O[nt][0] * inv0, O[nt][1] * inv0, hw, lw);
        *(uint2*)(AOw + off0) = make_uint2(hw, lw);
        split2(O[nt][2] * inv1, O[nt][3] * inv1, hw, lw);
        *(uint2*)(AOw + off1) = make_uint2(hw, lw);
    }
}

// ---------------------------------------------------------------------------
extern "C" void kernel_launch(void* const* d_in, const int* in_sizes, int n_in,
                              void* d_out, int out_size)
{
    const float* X  = (const float*)d_in[0];
    const float* Wq = (const float*)d_in[1];
    const float* Wk = (const float*)d_in[2];
    const float* Wv = (const float*)d_in[3];
    const float* Wo = (const float*)d_in[4];
    const float* bo = (const float*)d_in[5];
    float* out = (float*)d_out;

    const int mma_smem   = 2 * BUFSZ + 128;       // 82048
    const int flash_smem = 2 * FBUF + 128;        // 73856
    cudaFuncSetAttribute(qkv_mma, cudaFuncAttributeMaxDynamicSharedMemorySize, mma_smem);
    cudaFuncSetAttribute(out_mma, cudaFuncAttributeMaxDynamicSharedMemorySize, mma_smem);
    cudaFuncSetAttribute(flash_attn, cudaFuncAttributeMaxDynamicSharedMemorySize, flash_smem);

    split_x<<<4096, 256>>>(X, Mtot * Ev);
    split_w<<<dim3(32, 32, 4), 256>>>(Wq, Wk, Wv, Wo);

    qkv_mma<<<dim3(8, 256, 3), 256, mma_smem>>>();

    flash_attn<<<dim3(4, Hv, Bv), 256, flash_smem>>>();

    out_mma<<<dim3(8, 256), 256, mma_smem>>>(bo, out);
}

// round 16
// speedup vs baseline: 1.0566x; 1.0566x over previous
#include <cuda_runtime.h>
#include <cuda_bf16.h>

// Problem constants
#define Bv   64
#define Sv   512
#define Ev   1024
#define Hv   16
#define Dv   64
#define Mtot (Bv*Sv)   // 32768

// ---------------------------------------------------------------------------
// Scratch (__device__ globals; no allocation allowed).
// NOTE: reference these ONLY from device code (host-passed args bind the
// host-side shadow via GB300 ATS and silently corrupt).
// ---------------------------------------------------------------------------
__device__ __nv_bfloat16 g_Xhi [Mtot*Ev];     // X split, [M,K]
__device__ __nv_bfloat16 g_Xlo [Mtot*Ev];
__device__ __nv_bfloat16 g_Whi [4*Ev*Ev];     // W^T split, [N,K] per weight
__device__ __nv_bfloat16 g_Wlo [4*Ev*Ev];
__device__ __nv_bfloat16 g_Qhi [Mtot*Ev];     // [B,H,S,D] bf16 hi/lo
__device__ __nv_bfloat16 g_Qlo [Mtot*Ev];
__device__ __nv_bfloat16 g_Khi [Mtot*Ev];     // [B,H,S,D]
__device__ __nv_bfloat16 g_Klo [Mtot*Ev];
__device__ __nv_bfloat16 g_Vthi[Mtot*Ev];     // V transposed: [B,H,D,S]
__device__ __nv_bfloat16 g_Vtlo[Mtot*Ev];
__device__ __nv_bfloat16 g_AOhi[Mtot*Ev];     // attention out split, [B,S,E]
__device__ __nv_bfloat16 g_AOlo[Mtot*Ev];

// ---------------------------------------------------------------------------
// PTX helpers (Ampere-era: legal on plain sm_103 target)
// ---------------------------------------------------------------------------
__device__ __forceinline__ unsigned smem_u32(const void* p) {
    unsigned a;
    asm("{ .reg .u64 t; cvta.to.shared.u64 t, %1; cvt.u32.u64 %0, t; }" : "=r"(a) : "l"(p));
    return a;
}
__device__ __forceinline__ void cp_async16(unsigned s, const void* g) {
    asm volatile("cp.async.cg.shared.global [%0], [%1], 16;" :: "r"(s), "l"(g));
}
#define CP_COMMIT() asm volatile("cp.async.commit_group;" ::: "memory")
#define CP_WAIT(n)  asm volatile("cp.async.wait_group %0;" :: "n"(n) : "memory")

#define MMA_BF16(c, a, b) \
    asm volatile("mma.sync.aligned.m16n8k16.row.col.f32.bf16.bf16.f32 " \
        "{%0,%1,%2,%3}, {%4,%5,%6,%7}, {%8,%9}, {%0,%1,%2,%3};" \
        : "+f"((c)[0]), "+f"((c)[1]), "+f"((c)[2]), "+f"((c)[3]) \
        : "r"((a)[0]), "r"((a)[1]), "r"((a)[2]), "r"((a)[3]), \
          "r"((b)[0]), "r"((b)[1]))

// hi/lo bf16 split of a float pair, packed as bf16x2 words (low = first elem)
__device__ __forceinline__ void split2(float x0, float x1, unsigned& h, unsigned& l) {
    __nv_bfloat16 h0 = __float2bfloat16(x0), h1 = __float2bfloat16(x1);
    __nv_bfloat162 hh(h0, h1);
    __nv_bfloat162 ll(__float2bfloat16(x0 - __bfloat162float(h0)),
                      __float2bfloat16(x1 - __bfloat162float(h1)));
    h = *(unsigned*)&hh;
    l = *(unsigned*)&ll;
}

// Fast exp2 on the FMA/ALU pipes (keeps MUFU free). Input z = x*log2(e).
// Degree-4 poly on f in [0,1); coefficients sum to 1 so p(1)=2 exactly
// (continuity across integer boundaries). Max rel err ~1e-4.
__device__ __forceinline__ float fexp2(float z) {
    z = fmaxf(z, -126.f);                 // masked (-1e30) -> ~1e-38 ~ 0
    float fi = floorf(z);
    float f  = z - fi;
    float p  = 1.f + f*(0.69314718f + f*(0.24022651f
                   + f*(0.05550411f + f*0.01112215f)));
    return __int_as_float(((int)fi + 127) << 23) * p;
}
#define L2E 1.4426950408889634f

// ---------------------------------------------------------------------------
// Split / transpose precompute kernels (write device globals directly!)
// ---------------------------------------------------------------------------
__global__ __launch_bounds__(256)
void split_x(const float* __restrict__ in, int n)
{
    for (long long i = ((long long)blockIdx.x * 256 + threadIdx.x) * 4; i < n;
         i += (long long)gridDim.x * 1024) {
        float4 v = *(const float4*)(in + i);
        unsigned h0, l0, h1, l1;
        split2(v.x, v.y, h0, l0);
        split2(v.z, v.w, h1, l1);
        *(unsigned*)(g_Xhi + i)     = h0;
        *(unsigned*)(g_Xhi + i + 2) = h1;
        *(unsigned*)(g_Xlo + i)     = l0;
        *(unsigned*)(g_Xlo + i + 2) = l1;
    }
}

// W [K,N] fp32 -> W^T [N,K] bf16 hi/lo. grid (32,32,4), block 256 (32x8)
__global__ __launch_bounds__(256)
void split_w(const float* __restrict__ Wq, const float* __restrict__ Wk,
             const float* __restrict__ Wv, const float* __restrict__ Wo)
{
    __shared__ float t[32][33];
    const float* W = (blockIdx.z == 0) ? Wq : (blockIdx.z == 1) ? Wk
                     : (blockIdx.z == 2) ? Wv : Wo;
    const int n0 = blockIdx.x * 32, k0 = blockIdx.y * 32;
    const int tx = threadIdx.x & 31, ty = threadIdx.x >> 5;
    #pragma unroll
    for (int i = 0; i < 4; i++)
        t[ty + i*8][tx] = W[(size_t)(k0 + ty + i*8) * Ev + n0 + tx];
    __syncthreads();
    const size_t zo = (size_t)blockIdx.z * Ev * Ev;
    #pragma unroll
    for (int i = 0; i < 4; i++) {
        float x = t[tx][ty + i*8];
        __nv_bfloat16 h = __float2bfloat16(x);
        __nv_bfloat16 l = __float2bfloat16(x - __bfloat162float(h));
        size_t o = zo + (size_t)(n0 + ty + i*8) * Ev + k0 + tx;
        g_Whi[o] = h;
        g_Wlo[o] = l;
    }
}

// ---------------------------------------------------------------------------
// HMMA GEMM mainloop (R14 configuration — hardware-validated, fastest so far).
// ---------------------------------------------------------------------------
#define KITERS 32         // 1024 / 32
#define TILEB  10240      // 128 rows * 80 bytes
#define BUFSZ  40960      // 4 tiles (Ahi, Alo, Bhi, Blo)
#define ROWW   20         // words per smem row

__device__ __forceinline__ void hmma_gemm_tile(
    const __nv_bfloat16* __restrict__ Ah, const __nv_bfloat16* __restrict__ Al,
    const __nv_bfloat16* __restrict__ Bh, const __nv_bfloat16* __restrict__ Bl,
    char* smp, unsigned sbase, float acc[4][4][4])
{
    const int tid  = threadIdx.x;
    const int lane = tid & 31;
    const int wid  = tid >> 5;
    const int wm   = (wid & 1) * 64;
    const int wn   = (wid >> 1) * 32;
    const int fr   = lane >> 2;     // 0..7
    const int ft   = lane & 3;      // 0..3

    auto fill = [&](int buf, int k0) {
        const unsigned boff = sbase + buf * BUFSZ;
        #pragma unroll
        for (int it = 0; it < 8; ++it) {
            const int t = it >> 1;
            int e = tid + (it & 1) * 256;
            int r = e >> 2, c = e & 3;
            const __nv_bfloat16* gb = (t == 0) ? Ah : (t == 1) ? Al
                                     : (t == 2) ? Bh : Bl;
            cp_async16(boff + t * TILEB + r * 80 + c * 16,
                       gb + (size_t)r * Ev + k0 + c * 8);
        }
    };

    fill(0, 0); CP_COMMIT();

    for (int cIt = 0; cIt < KITERS; ++cIt) {
        const int buf = cIt & 1;
        if (cIt + 1 < KITERS) { fill(buf ^ 1, (cIt + 1) * 32); CP_COMMIT(); CP_WAIT(1); }
        else                  { CP_WAIT(0); }
        __syncthreads();

        const unsigned* A_h = (const unsigned*)(smp + buf * BUFSZ);
        const unsigned* A_l = (const unsigned*)(smp + buf * BUFSZ + TILEB);
        const unsigned* B_h = (const unsigned*)(smp + buf * BUFSZ + 2 * TILEB);
        const unsigned* B_l = (const unsigned*)(smp + buf * BUFSZ + 3 * TILEB);

        #pragma unroll
        for (int ks2 = 0; ks2 < 16; ks2 += 8) {
            unsigned bh[4][2], bl[4][2];
            #pragma unroll
            for (int na = 0; na < 4; ++na) {
                int base = (wn + na * 8 + fr) * ROWW + ks2 + ft;
                bh[na][0] = B_h[base];  bh[na][1] = B_h[base + 4];
                bl[na][0] = B_l[base];  bl[na][1] = B_l[base + 4];
            }
            #pragma unroll
            for (int ma = 0; ma < 4; ++ma) {
                int ab = (wm + ma * 16 + fr) * ROWW + ks2 + ft;
                unsigned ah[4], al[4];
                ah[0] = A_h[ab];            ah[1] = A_h[ab + 8 * ROWW];
                ah[2] = A_h[ab + 4];        ah[3] = A_h[ab + 8 * ROWW + 4];
                al[0] = A_l[ab];            al[1] = A_l[ab + 8 * ROWW];
                al[2] = A_l[ab + 4];        al[3] = A_l[ab + 8 * ROWW + 4];
                #pragma unroll
                for (int na = 0; na < 4; ++na) {
                    MMA_BF16(acc[ma][na], ah, bh[na]);
                    MMA_BF16(acc[ma][na], ah, bl[na]);
                    MMA_BF16(acc[ma][na], al, bh[na]);
                }
            }
        }
        __syncthreads();
    }
}

// ---------------------------------------------------------------------------
// QKV: X @ {Wq,Wk,Wv}. Epilogue writes bf16 hi/lo:
//   z=0 -> Q [B,H,S,D], z=1 -> K [B,H,S,D], z=2 -> V^T [B,H,D,S]
// grid (8, 256, 3)
// ---------------------------------------------------------------------------
__global__ __launch_bounds__(256, 2)
void qkv_mma()
{
    extern __shared__ char dsm[];
    unsigned raw   = smem_u32(dsm);
    unsigned sbase = (raw + 127) & ~127u;
    char* smp = dsm + (sbase - raw);

    const int z    = blockIdx.z;
    const int row0 = blockIdx.y * 128;
    const int col0 = blockIdx.x * 128;
    const size_t wz = (size_t)z * Ev * Ev;

    float acc[4][4][4] = {};
    hmma_gemm_tile(g_Xhi + (size_t)row0 * Ev, g_Xlo + (size_t)row0 * Ev,
                   g_Whi + wz + (size_t)col0 * Ev, g_Wlo + wz + (size_t)col0 * Ev,
                   smp, sbase, acc);

    const int lane = threadIdx.x & 31, wid = threadIdx.x >> 5;
    const int wm = (wid & 1) * 64, wn = (wid >> 1) * 32;
    const int grp = lane >> 2, tig = lane & 3;

    if (z < 2) {
        __nv_bfloat16* Ohi = (z == 0) ? g_Qhi : g_Khi;
        __nv_bfloat16* Olo = (z == 0) ? g_Qlo : g_Klo;
        #pragma unroll
        for (int ma = 0; ma < 4; ++ma) {
            #pragma unroll
            for (int na = 0; na < 4; ++na) {
                int n = col0 + wn + na * 8 + tig * 2;
                int h = n >> 6, d = n & 63;
                #pragma unroll
                for (int half = 0; half < 2; ++half) {
                    int m = row0 + wm + ma * 16 + grp + half * 8;
                    int b = m >> 9, s = m & 511;
                    size_t off = ((size_t)(b * Hv + h) * Sv + s) * Dv + d;
                    unsigned hw, lw;
                    split2(acc[ma][na][half*2], acc[ma][na][half*2+1], hw, lw);
                    *(unsigned*)(Ohi + off) = hw;
                    *(unsigned*)(Olo + off) = lw;
                }
            }
        }
    } else {
        #pragma unroll
        for (int ma = 0; ma < 4; ++ma) {
            #pragma unroll
            for (int na = 0; na < 4; ++na) {
                int n = col0 + wn + na * 8 + tig * 2;
                int h = n >> 6, d = n & 63;
                #pragma unroll
                for (int half = 0; half < 2; ++half) {
                    int m = row0 + wm + ma * 16 + grp + half * 8;
                    int b = m >> 9, s = m & 511;
                    #pragma unroll
                    for (int e = 0; e < 2; ++e) {
                        float x = acc[ma][na][half*2 + e];
                        __nv_bfloat16 hh = __float2bfloat16(x);
                        __nv_bfloat16 ll = __float2bfloat16(x - __bfloat162float(hh));
                        size_t off = ((size_t)(b * Hv + h) * Dv + d + e) * Sv + s;
                        g_Vthi[off] = hh;
                        g_Vtlo[off] = ll;
                    }
                }
            }
        }
    }
}

// ---------------------------------------------------------------------------
// Output projection: AO @ Wo + bo -> out.  grid (8, 256)
// ---------------------------------------------------------------------------
__global__ __launch_bounds__(256, 2)
void out_mma(const float* __restrict__ bo, float* __restrict__ Cout)
{
    extern __shared__ char dsm[];
    unsigned raw   = smem_u32(dsm);
    unsigned sbase = (raw + 127) & ~127u;
    char* smp = dsm + (sbase - raw);

    const int row0 = blockIdx.y * 128;
    const int col0 = blockIdx.x * 128;
    const size_t wz = (size_t)3 * Ev * Ev;

    float acc[4][4][4] = {};
    hmma_gemm_tile(g_AOhi + (size_t)row0 * Ev, g_AOlo + (size_t)row0 * Ev,
                   g_Whi + wz + (size_t)col0 * Ev, g_Wlo + wz + (size_t)col0 * Ev,
                   smp, sbase, acc);

    const int lane = threadIdx.x & 31, wid = threadIdx.x >> 5;
    const int wm = (wid & 1) * 64, wn = (wid >> 1) * 32;
    const int grp = lane >> 2, tig = lane & 3;

    #pragma unroll
    for (int ma = 0; ma < 4; ++ma) {
        #pragma unroll
        for (int na = 0; na < 4; ++na) {
            int n = col0 + wn + na * 8 + tig * 2;
            float2 bia = *(const float2*)(bo + n);
            #pragma unroll
            for (int half = 0; half < 2; ++half) {
                int m = row0 + wm + ma * 16 + grp + half * 8;
                float* dst = Cout + (size_t)m * Ev + n;
                *(float2*)dst = make_float2(acc[ma][na][half*2]   + bia.x,
                                            acc[ma][na][half*2+1] + bia.y);
            }
        }
    }
}

// ---------------------------------------------------------------------------
// Tensorized flash attention (causal, NO 1/sqrt(d) scale).
// R14 structure; softmax exp moved off MUFU onto FMA/ALU pipes via fexp2.
// ---------------------------------------------------------------------------
#define TROW 36                 // words per smem row
#define TSZ  (64 * TROW * 4)    // 9216 B per tile
#define FBUF (4 * TSZ)          // 36864 B per buffer (Kh, Kl, Vth, Vtl)

__global__ __launch_bounds__(256, 2)
void flash_attn()
{
    extern __shared__ char dsm[];
    unsigned raw   = smem_u32(dsm);
    unsigned sbase = (raw + 127) & ~127u;
    char* smp = dsm + (sbase - raw);

    const int qt = blockIdx.x;          // 0..3 (128-row q tiles)
    const int h  = blockIdx.y;
    const int b  = blockIdx.z;
    const int q0 = qt * 128;

    const int tid  = threadIdx.x;
    const int lane = tid & 31;
    const int wid  = tid >> 5;
    const int grp  = lane >> 2;         // 0..7
    const int ft   = lane & 3;          // 0..3
    const int wm   = wid * 16;

    const long long bh = (long long)b * Hv + h;

    // Q fragments (persistent in registers): rows q0+wm .. +15, 32 words/row
    const unsigned* Qhw = (const unsigned*)g_Qhi + (bh * Sv + q0 + wm) * 32;
    const unsigned* Qlw = (const unsigned*)g_Qlo + (bh * Sv + q0 + wm) * 32;
    unsigned qh[4][4], ql[4][4];
    #pragma unroll
    for (int kc = 0; kc < 4; ++kc) {
        int w0 = grp * 32 + kc * 8 + ft;
        qh[kc][0] = Qhw[w0];       qh[kc][1] = Qhw[w0 + 256];
        qh[kc][2] = Qhw[w0 + 4];   qh[kc][3] = Qhw[w0 + 260];
        ql[kc][0] = Qlw[w0];       ql[kc][1] = Qlw[w0 + 256];
        ql[kc][2] = Qlw[w0 + 4];   ql[kc][3] = Qlw[w0 + 260];
    }

    const __nv_bfloat16* Kh  = g_Khi  + bh * Sv * Dv;
    const __nv_bfloat16* Kl  = g_Klo  + bh * Sv * Dv;
    const __nv_bfloat16* Vth = g_Vthi + bh * Dv * Sv;
    const __nv_bfloat16* Vtl = g_Vtlo + bh * Dv * Sv;

    float O[8][4] = {};
    float m0 = -1e30f, m1 = -1e30f, l0 = 0.f, l1 = 0.f;

    const int kbmax = 2 * (qt + 1);

    auto fill = [&](int buf, int kb) {
        const unsigned boff = sbase + buf * FBUF;
        #pragma unroll
        for (int it = 0; it < 8; ++it) {
            const int t = it >> 1;
            int e = tid + (it & 1) * 256;     // 0..511
            int r = e >> 3, c = e & 7;
            const __nv_bfloat16* g;
            if      (t == 0) g = Kh  + (size_t)(kb * 64 + r) * Dv + c * 8;
            else if (t == 1) g = Kl  + (size_t)(kb * 64 + r) * Dv + c * 8;
            else if (t == 2) g = Vth + (size_t)r * Sv + kb * 64 + c * 8;
            else             g = Vtl + (size_t)r * Sv + kb * 64 + c * 8;
            cp_async16(boff + t * TSZ + r * 144 + c * 16, g);
        }
    };

    fill(0, 0); CP_COMMIT();

    for (int kb = 0; kb < kbmax; ++kb) {
        const int buf = kb & 1;
        if (kb + 1 < kbmax) { fill(buf ^ 1, kb + 1); CP_COMMIT(); CP_WAIT(1); }
        else                { CP_WAIT(0); }
        __syncthreads();

        const unsigned* SK_h = (const unsigned*)(smp + buf * FBUF);
        const unsigned* SK_l = (const unsigned*)(smp + buf * FBUF + TSZ);
        const unsigned* SV_h = (const unsigned*)(smp + buf * FBUF + 2 * TSZ);
        const unsigned* SV_l = (const unsigned*)(smp + buf * FBUF + 3 * TSZ);

        // S = Q @ K^T (16x64 per warp), 3-term split
        float sacc[8][4] = {};
        #pragma unroll
        for (int kc = 0; kc < 4; ++kc) {
            unsigned bhf[8][2], blf[8][2];
            #pragma unroll
            for (int nt = 0; nt < 8; ++nt) {
                int w = (nt * 8 + grp) * TROW + kc * 8 + ft;
                bhf[nt][0] = SK_h[w];  bhf[nt][1] = SK_h[w + 4];
                blf[nt][0] = SK_l[w];  blf[nt][1] = SK_l[w + 4];
            }
            #pragma unroll
            for (int nt = 0; nt < 8; ++nt) {
                MMA_BF16(sacc[nt], qh[kc], bhf[nt]);
                MMA_BF16(sacc[nt], qh[kc], blf[nt]);
                MMA_BF16(sacc[nt], ql[kc], bhf[nt]);
            }
        }

        // causal mask (only the last two key blocks can cross the diagonal)
        if (kb >= kbmax - 2) {
            int r0 = q0 + wm + grp, r1 = r0 + 8;
            #pragma unroll
            for (int nt = 0; nt < 8; ++nt) {
                int c0 = kb * 64 + nt * 8 + 2 * ft;
                if (c0     > r0) sacc[nt][0] = -1e30f;
                if (c0 + 1 > r0) sacc[nt][1] = -1e30f;
                if (c0     > r1) sacc[nt][2] = -1e30f;
                if (c0 + 1 > r1) sacc[nt][3] = -1e30f;
            }
        }

        // online softmax in registers (rows grp / grp+8; quad holds full row)
        float mx0 = -1e30f, mx1 = -1e30f;
        #pragma unroll
        for (int nt = 0; nt < 8; ++nt) {
            mx0 = fmaxf(mx0, fmaxf(sacc[nt][0], sacc[nt][1]));
            mx1 = fmaxf(mx1, fmaxf(sacc[nt][2], sacc[nt][3]));
        }
        mx0 = fmaxf(mx0, __shfl_xor_sync(0xffffffffu, mx0, 1));
        mx0 = fmaxf(mx0, __shfl_xor_sync(0xffffffffu, mx0, 2));
        mx1 = fmaxf(mx1, __shfl_xor_sync(0xffffffffu, mx1, 1));
        mx1 = fmaxf(mx1, __shfl_xor_sync(0xffffffffu, mx1, 2));

        float mn0 = fmaxf(m0, mx0), mn1 = fmaxf(m1, mx1);
        float al0 = __expf(m0 - mn0), al1 = __expf(m1 - mn1);
        float nb0 = mn0 * L2E, nb1 = mn1 * L2E;   // row bias in log2 domain
        float ps0 = 0.f, ps1 = 0.f;
        #pragma unroll
        for (int nt = 0; nt < 8; ++nt) {
            sacc[nt][0] = fexp2(fmaf(sacc[nt][0], L2E, -nb0));
            sacc[nt][1] = fexp2(fmaf(sacc[nt][1], L2E, -nb0));
            sacc[nt][2] = fexp2(fmaf(sacc[nt][2], L2E, -nb1));
            sacc[nt][3] = fexp2(fmaf(sacc[nt][3], L2E, -nb1));
            ps0 += sacc[nt][0] + sacc[nt][1];
            ps1 += sacc[nt][2] + sacc[nt][3];
        }
        ps0 += __shfl_xor_sync(0xffffffffu, ps0, 1);
        ps0 += __shfl_xor_sync(0xffffffffu, ps0, 2);
        ps1 += __shfl_xor_sync(0xffffffffu, ps1, 1);
        ps1 += __shfl_xor_sync(0xffffffffu, ps1, 2);
        l0 = l0 * al0 + ps0;  l1 = l1 * al1 + ps1;
        m0 = mn0;             m1 = mn1;
        #pragma unroll
        for (int nt = 0; nt < 8; ++nt) {
            O[nt][0] *= al0;  O[nt][1] *= al0;
            O[nt][2] *= al1;  O[nt][3] *= al1;
        }

        // repack P (C layout -> A fragments, hi/lo split), lane-local
        unsigned ph[4][4], pl[4][4];
        #pragma unroll
        for (int kc = 0; kc < 4; ++kc) {
            split2(sacc[2*kc][0],   sacc[2*kc][1],   ph[kc][0], pl[kc][0]);
            split2(sacc[2*kc][2],   sacc[2*kc][3],   ph[kc][1], pl[kc][1]);
            split2(sacc[2*kc+1][0], sacc[2*kc+1][1], ph[kc][2], pl[kc][2]);
            split2(sacc[2*kc+1][2], sacc[2*kc+1][3], ph[kc][3], pl[kc][3]);
        }

        // O += P @ V  (V^T tile in smem is exactly B-fragment layout)
        #pragma unroll
        for (int kc = 0; kc < 4; ++kc) {
            unsigned vh[8][2], vl[8][2];
            #pragma unroll
            for (int nt = 0; nt < 8; ++nt) {
                int w = (nt * 8 + grp) * TROW + kc * 8 + ft;
                vh[nt][0] = SV_h[w];  vh[nt][1] = SV_h[w + 4];
                vl[nt][0] = SV_l[w];  vl[nt][1] = SV_l[w + 4];
            }
            #pragma unroll
            for (int nt = 0; nt < 8; ++nt) {
                MMA_BF16(O[nt], ph[kc], vh[nt]);
                MMA_BF16(O[nt], ph[kc], vl[nt]);
                MMA_BF16(O[nt], pl[kc], vh[nt]);
            }
        }
        __syncthreads();
    }

    // normalize + write AO hi/lo split into [B,S,E]
    float inv0 = 1.f / l0, inv1 = 1.f / l1;
    int r0 = q0 + wm + grp, r1 = r0 + 8;
    #pragma unroll
    for (int nt = 0; nt < 8; ++nt) {
        int d = nt * 8 + 2 * ft;
        size_t off0 = ((size_t)b * Sv + r0) * Ev + h * 64 + d;
        size_t off1 = ((size_t)b * Sv + r1) * Ev + h * 64 + d;
        unsigned hw, lw;
        split2(O[nt][0] * inv0, O[nt][1] * inv0, hw, lw);
        *(unsigned*)(g_AOhi + off0) = hw;
        *(unsigned*)(g_AOlo + off0) = lw;
        split2(O[nt][2] * inv1, O[nt][3] * inv1, hw, lw);
        *(unsigned*)(g_AOhi + off1) = hw;
        *(unsigned*)(g_AOlo + off1) = lw;
    }
}

// ---------------------------------------------------------------------------
extern "C" void kernel_launch(void* const* d_in, const int* in_sizes, int n_in,
                              void* d_out, int out_size)
{
    const float* X  = (const float*)d_in[0];
    const float* Wq = (const float*)d_in[1];
    const float* Wk = (const float*)d_in[2];
    const float* Wv = (const float*)d_in[3];
    const float* Wo = (const float*)d_in[4];
    const float* bo = (const float*)d_in[5];
    float* out = (float*)d_out;

    const int mma_smem   = 2 * BUFSZ + 128;       // 82048
    const int flash_smem = 2 * FBUF + 128;        // 73856
    cudaFuncSetAttribute(qkv_mma, cudaFuncAttributeMaxDynamicSharedMemorySize, mma_smem);
    cudaFuncSetAttribute(out_mma, cudaFuncAttributeMaxDynamicSharedMemorySize, mma_smem);
    cudaFuncSetAttribute(flash_attn, cudaFuncAttributeMaxDynamicSharedMemorySize, flash_smem);

    split_x<<<4096, 256>>>(X, Mtot * Ev);
    split_w<<<dim3(32, 32, 4), 256>>>(Wq, Wk, Wv, Wo);

    qkv_mma<<<dim3(8, 256, 3), 256, mma_smem>>>();

    flash_attn<<<dim3(4, Hv, Bv), 256, flash_smem>>>();

    out_mma<<<dim3(8, 256), 256, mma_smem>>>(bo, out);
}

// round 17
// speedup vs baseline: 1.1614x; 1.0992x over previous
#include <cuda_runtime.h>
#include <cuda_bf16.h>

// Problem constants
#define Bv   64
#define Sv   512
#define Ev   1024
#define Hv   16
#define Dv   64
#define Mtot (Bv*Sv)   // 32768

// ---------------------------------------------------------------------------
// Scratch (__device__ globals; no allocation allowed).
// NOTE: reference these ONLY from device code (host-passed args bind the
// host-side shadow via GB300 ATS and silently corrupt).
// ---------------------------------------------------------------------------
__device__ __nv_bfloat16 g_Xhi [Mtot*Ev];     // X split, [M,K]
__device__ __nv_bfloat16 g_Xlo [Mtot*Ev];
__device__ __nv_bfloat16 g_Whi [4*Ev*Ev];     // W^T split, [N,K] per weight
__device__ __nv_bfloat16 g_Wlo [4*Ev*Ev];
__device__ __nv_bfloat16 g_Qhi [Mtot*Ev];     // [B,H,S,D] bf16 hi/lo
__device__ __nv_bfloat16 g_Qlo [Mtot*Ev];
__device__ __nv_bfloat16 g_Khi [Mtot*Ev];     // [B,H,S,D]
__device__ __nv_bfloat16 g_Klo [Mtot*Ev];
__device__ __nv_bfloat16 g_Vthi[Mtot*Ev];     // V transposed: [B,H,D,S]
__device__ __nv_bfloat16 g_Vtlo[Mtot*Ev];
__device__ __nv_bfloat16 g_AOhi[Mtot*Ev];     // attention out split, [B,S,E]
__device__ __nv_bfloat16 g_AOlo[Mtot*Ev];

// ---------------------------------------------------------------------------
// PTX helpers (Ampere-era: legal on plain sm_103 target)
// ---------------------------------------------------------------------------
__device__ __forceinline__ unsigned smem_u32(const void* p) {
    unsigned a;
    asm("{ .reg .u64 t; cvta.to.shared.u64 t, %1; cvt.u32.u64 %0, t; }" : "=r"(a) : "l"(p));
    return a;
}
__device__ __forceinline__ void cp_async16(unsigned s, const void* g) {
    asm volatile("cp.async.cg.shared.global [%0], [%1], 16;" :: "r"(s), "l"(g));
}
#define CP_COMMIT() asm volatile("cp.async.commit_group;" ::: "memory")
#define CP_WAIT(n)  asm volatile("cp.async.wait_group %0;" :: "n"(n) : "memory")

#define MMA_BF16(c, a, b) \
    asm volatile("mma.sync.aligned.m16n8k16.row.col.f32.bf16.bf16.f32 " \
        "{%0,%1,%2,%3}, {%4,%5,%6,%7}, {%8,%9}, {%0,%1,%2,%3};" \
        : "+f"((c)[0]), "+f"((c)[1]), "+f"((c)[2]), "+f"((c)[3]) \
        : "r"((a)[0]), "r"((a)[1]), "r"((a)[2]), "r"((a)[3]), \
          "r"((b)[0]), "r"((b)[1]))

#define LDSM_X4(r, a) \
    asm volatile("ldmatrix.sync.aligned.m8n8.x4.shared.b16 {%0,%1,%2,%3}, [%4];" \
        : "=r"((r)[0]), "=r"((r)[1]), "=r"((r)[2]), "=r"((r)[3]) : "r"(a))

// hi/lo bf16 split of a float pair, packed as bf16x2 words (low = first elem)
__device__ __forceinline__ void split2(float x0, float x1, unsigned& h, unsigned& l) {
    __nv_bfloat16 h0 = __float2bfloat16(x0), h1 = __float2bfloat16(x1);
    __nv_bfloat162 hh(h0, h1);
    __nv_bfloat162 ll(__float2bfloat16(x0 - __bfloat162float(h0)),
                      __float2bfloat16(x1 - __bfloat162float(h1)));
    h = *(unsigned*)&hh;
    l = *(unsigned*)&ll;
}

// ---------------------------------------------------------------------------
// Split / transpose precompute kernels (write device globals directly!)
// ---------------------------------------------------------------------------
__global__ __launch_bounds__(256)
void split_x(const float* __restrict__ in, int n)
{
    for (long long i = ((long long)blockIdx.x * 256 + threadIdx.x) * 4; i < n;
         i += (long long)gridDim.x * 1024) {
        float4 v = *(const float4*)(in + i);
        unsigned h0, l0, h1, l1;
        split2(v.x, v.y, h0, l0);
        split2(v.z, v.w, h1, l1);
        *(unsigned*)(g_Xhi + i)     = h0;
        *(unsigned*)(g_Xhi + i + 2) = h1;
        *(unsigned*)(g_Xlo + i)     = l0;
        *(unsigned*)(g_Xlo + i + 2) = l1;
    }
}

// W [K,N] fp32 -> W^T [N,K] bf16 hi/lo. grid (32,32,4), block 256 (32x8)
__global__ __launch_bounds__(256)
void split_w(const float* __restrict__ Wq, const float* __restrict__ Wk,
             const float* __restrict__ Wv, const float* __restrict__ Wo)
{
    __shared__ float t[32][33];
    const float* W = (blockIdx.z == 0) ? Wq : (blockIdx.z == 1) ? Wk
                     : (blockIdx.z == 2) ? Wv : Wo;
    const int n0 = blockIdx.x * 32, k0 = blockIdx.y * 32;
    const int tx = threadIdx.x & 31, ty = threadIdx.x >> 5;
    #pragma unroll
    for (int i = 0; i < 4; i++)
        t[ty + i*8][tx] = W[(size_t)(k0 + ty + i*8) * Ev + n0 + tx];
    __syncthreads();
    const size_t zo = (size_t)blockIdx.z * Ev * Ev;
    #pragma unroll
    for (int i = 0; i < 4; i++) {
        float x = t[tx][ty + i*8];
        __nv_bfloat16 h = __float2bfloat16(x);
        __nv_bfloat16 l = __float2bfloat16(x - __bfloat162float(h));
        size_t o = zo + (size_t)(n0 + ty + i*8) * Ev + k0 + tx;
        g_Whi[o] = h;
        g_Wlo[o] = l;
    }
}

// ---------------------------------------------------------------------------
// HMMA GEMM mainloop (R14 layout) with ldmatrix.x4 fragment loads.
// 80 B row stride: LDSM rows start at banks 20r mod 32 = {0,20,8,28,16,4,24,12},
// 4 words each -> all 32 banks exactly once: conflict-free.
// ---------------------------------------------------------------------------
#define KITERS 32         // 1024 / 32
#define TILEB  10240      // 128 rows * 80 bytes
#define BUFSZ  40960      // 4 tiles (Ahi, Alo, Bhi, Blo)

__device__ __forceinline__ void hmma_gemm_tile(
    const __nv_bfloat16* __restrict__ Ah, const __nv_bfloat16* __restrict__ Al,
    const __nv_bfloat16* __restrict__ Bh, const __nv_bfloat16* __restrict__ Bl,
    unsigned sbase, float acc[4][4][4])
{
    const int tid  = threadIdx.x;
    const int lane = tid & 31;
    const int wid  = tid >> 5;
    const int wm   = (wid & 1) * 64;
    const int wn   = (wid >> 1) * 32;

    // ldmatrix per-lane addressing components
    const int a_row = ((lane >> 3) & 1) * 8 + (lane & 7);  // A: m0 r0-7,m1 r8-15,m2 r0-7,m3 r8-15
    const int a_cb  = (lane >> 4) * 16;                    //    m0/m1 kseg0, m2/m3 kseg1
    const int b_row = ((lane >> 4) << 3) + (lane & 7);     // B: m0/m1 n0-7, m2/m3 n8-15
    const int b_cb  = ((lane >> 3) & 1) * 16;              //    m0 ks0, m1 ks1 per n-oct

    auto fill = [&](int buf, int k0) {
        const unsigned boff = sbase + buf * BUFSZ;
        #pragma unroll
        for (int it = 0; it < 8; ++it) {
            const int t = it >> 1;
            int e = tid + (it & 1) * 256;
            int r = e >> 2, c = e & 3;
            const __nv_bfloat16* gb = (t == 0) ? Ah : (t == 1) ? Al
                                     : (t == 2) ? Bh : Bl;
            cp_async16(boff + t * TILEB + r * 80 + c * 16,
                       gb + (size_t)r * Ev + k0 + c * 8);
        }
    };

    fill(0, 0); CP_COMMIT();

    for (int cIt = 0; cIt < KITERS; ++cIt) {
        const int buf = cIt & 1;
        if (cIt + 1 < KITERS) { fill(buf ^ 1, (cIt + 1) * 32); CP_COMMIT(); CP_WAIT(1); }
        else                  { CP_WAIT(0); }
        __syncthreads();

        const unsigned tA_h = sbase + buf * BUFSZ;
        const unsigned tA_l = tA_h + TILEB;
        const unsigned tB_h = tA_h + 2 * TILEB;
        const unsigned tB_l = tA_h + 3 * TILEB;

        #pragma unroll
        for (int ks2 = 0; ks2 < 16; ks2 += 8) {     // word offset of 16-k chunk
            unsigned bh[4][2], bl[4][2];
            #pragma unroll
            for (int np = 0; np < 2; ++np) {
                unsigned off = (unsigned)(wn + np * 16 + b_row) * 80 + ks2 * 4 + b_cb;
                unsigned r4[4];
                LDSM_X4(r4, tB_h + off);
                bh[np*2][0] = r4[0];  bh[np*2][1] = r4[1];
                bh[np*2+1][0] = r4[2]; bh[np*2+1][1] = r4[3];
                LDSM_X4(r4, tB_l + off);
                bl[np*2][0] = r4[0];  bl[np*2][1] = r4[1];
                bl[np*2+1][0] = r4[2]; bl[np*2+1][1] = r4[3];
            }
            #pragma unroll
            for (int ma = 0; ma < 4; ++ma) {
                unsigned off = (unsigned)(wm + ma * 16 + a_row) * 80 + ks2 * 4 + a_cb;
                unsigned ah[4], al[4];
                LDSM_X4(ah, tA_h + off);
                LDSM_X4(al, tA_l + off);
                #pragma unroll
                for (int na = 0; na < 4; ++na) {
                    MMA_BF16(acc[ma][na], ah, bh[na]);
                    MMA_BF16(acc[ma][na], ah, bl[na]);
                    MMA_BF16(acc[ma][na], al, bh[na]);
                }
            }
        }
        __syncthreads();
    }
}

// ---------------------------------------------------------------------------
// QKV: X @ {Wq,Wk,Wv}. Epilogue writes bf16 hi/lo:
//   z=0 -> Q [B,H,S,D], z=1 -> K [B,H,S,D], z=2 -> V^T [B,H,D,S]
// grid (8, 256, 3)
// ---------------------------------------------------------------------------
__global__ __launch_bounds__(256, 2)
void qkv_mma()
{
    extern __shared__ char dsm[];
    unsigned raw   = smem_u32(dsm);
    unsigned sbase = (raw + 127) & ~127u;

    const int z    = blockIdx.z;
    const int row0 = blockIdx.y * 128;
    const int col0 = blockIdx.x * 128;
    const size_t wz = (size_t)z * Ev * Ev;

    float acc[4][4][4] = {};
    hmma_gemm_tile(g_Xhi + (size_t)row0 * Ev, g_Xlo + (size_t)row0 * Ev,
                   g_Whi + wz + (size_t)col0 * Ev, g_Wlo + wz + (size_t)col0 * Ev,
                   sbase, acc);

    const int lane = threadIdx.x & 31, wid = threadIdx.x >> 5;
    const int wm = (wid & 1) * 64, wn = (wid >> 1) * 32;
    const int grp = lane >> 2, tig = lane & 3;

    if (z < 2) {
        __nv_bfloat16* Ohi = (z == 0) ? g_Qhi : g_Khi;
        __nv_bfloat16* Olo = (z == 0) ? g_Qlo : g_Klo;
        #pragma unroll
        for (int ma = 0; ma < 4; ++ma) {
            #pragma unroll
            for (int na = 0; na < 4; ++na) {
                int n = col0 + wn + na * 8 + tig * 2;
                int h = n >> 6, d = n & 63;
                #pragma unroll
                for (int half = 0; half < 2; ++half) {
                    int m = row0 + wm + ma * 16 + grp + half * 8;
                    int b = m >> 9, s = m & 511;
                    size_t off = ((size_t)(b * Hv + h) * Sv + s) * Dv + d;
                    unsigned hw, lw;
                    split2(acc[ma][na][half*2], acc[ma][na][half*2+1], hw, lw);
                    *(unsigned*)(Ohi + off) = hw;
                    *(unsigned*)(Olo + off) = lw;
                }
            }
        }
    } else {
        #pragma unroll
        for (int ma = 0; ma < 4; ++ma) {
            #pragma unroll
            for (int na = 0; na < 4; ++na) {
                int n = col0 + wn + na * 8 + tig * 2;
                int h = n >> 6, d = n & 63;
                #pragma unroll
                for (int half = 0; half < 2; ++half) {
                    int m = row0 + wm + ma * 16 + grp + half * 8;
                    int b = m >> 9, s = m & 511;
                    #pragma unroll
                    for (int e = 0; e < 2; ++e) {
                        float x = acc[ma][na][half*2 + e];
                        __nv_bfloat16 hh = __float2bfloat16(x);
                        __nv_bfloat16 ll = __float2bfloat16(x - __bfloat162float(hh));
                        size_t off = ((size_t)(b * Hv + h) * Dv + d + e) * Sv + s;
                        g_Vthi[off] = hh;
                        g_Vtlo[off] = ll;
                    }
                }
            }
        }
    }
}

// ---------------------------------------------------------------------------
// Output projection: AO @ Wo + bo -> out.  grid (8, 256)
// ---------------------------------------------------------------------------
__global__ __launch_bounds__(256, 2)
void out_mma(const float* __restrict__ bo, float* __restrict__ Cout)
{
    extern __shared__ char dsm[];
    unsigned raw   = smem_u32(dsm);
    unsigned sbase = (raw + 127) & ~127u;

    const int row0 = blockIdx.y * 128;
    const int col0 = blockIdx.x * 128;
    const size_t wz = (size_t)3 * Ev * Ev;

    float acc[4][4][4] = {};
    hmma_gemm_tile(g_AOhi + (size_t)row0 * Ev, g_AOlo + (size_t)row0 * Ev,
                   g_Whi + wz + (size_t)col0 * Ev, g_Wlo + wz + (size_t)col0 * Ev,
                   sbase, acc);

    const int lane = threadIdx.x & 31, wid = threadIdx.x >> 5;
    const int wm = (wid & 1) * 64, wn = (wid >> 1) * 32;
    const int grp = lane >> 2, tig = lane & 3;

    #pragma unroll
    for (int ma = 0; ma < 4; ++ma) {
        #pragma unroll
        for (int na = 0; na < 4; ++na) {
            int n = col0 + wn + na * 8 + tig * 2;
            float2 bia = *(const float2*)(bo + n);
            #pragma unroll
            for (int half = 0; half < 2; ++half) {
                int m = row0 + wm + ma * 16 + grp + half * 8;
                float* dst = Cout + (size_t)m * Ev + n;
                *(float2*)dst = make_float2(acc[ma][na][half*2]   + bia.x,
                                            acc[ma][na][half*2+1] + bia.y);
            }
        }
    }
}

// ---------------------------------------------------------------------------
// Tensorized flash attention (causal, NO 1/sqrt(d) scale).
// R14 structure (__expf softmax) with ldmatrix.x4 K/V fragment loads.
// 144 B row stride: LDSM rows start at banks 4r mod 32 -> all 32 banks once.
// ---------------------------------------------------------------------------
#define TROW 36                 // words per smem row
#define TSZ  (64 * TROW * 4)    // 9216 B per tile
#define FBUF (4 * TSZ)          // 36864 B per buffer (Kh, Kl, Vth, Vtl)

__global__ __launch_bounds__(256, 2)
void flash_attn()
{
    extern __shared__ char dsm[];
    unsigned raw   = smem_u32(dsm);
    unsigned sbase = (raw + 127) & ~127u;

    const int qt = blockIdx.x;          // 0..3 (128-row q tiles)
    const int h  = blockIdx.y;
    const int b  = blockIdx.z;
    const int q0 = qt * 128;

    const int tid  = threadIdx.x;
    const int lane = tid & 31;
    const int wid  = tid >> 5;
    const int grp  = lane >> 2;         // 0..7
    const int ft   = lane & 3;          // 0..3
    const int wm   = wid * 16;

    // ldmatrix B-fragment lane addressing
    const int f_row = ((lane >> 4) << 3) + (lane & 7);
    const int f_cb  = ((lane >> 3) & 1) * 16;

    const long long bh = (long long)b * Hv + h;

    // Q fragments (persistent in registers): rows q0+wm .. +15, 32 words/row
    const unsigned* Qhw = (const unsigned*)g_Qhi + (bh * Sv + q0 + wm) * 32;
    const unsigned* Qlw = (const unsigned*)g_Qlo + (bh * Sv + q0 + wm) * 32;
    unsigned qh[4][4], ql[4][4];
    #pragma unroll
    for (int kc = 0; kc < 4; ++kc) {
        int w0 = grp * 32 + kc * 8 + ft;
        qh[kc][0] = Qhw[w0];       qh[kc][1] = Qhw[w0 + 256];
        qh[kc][2] = Qhw[w0 + 4];   qh[kc][3] = Qhw[w0 + 260];
        ql[kc][0] = Qlw[w0];       ql[kc][1] = Qlw[w0 + 256];
        ql[kc][2] = Qlw[w0 + 4];   ql[kc][3] = Qlw[w0 + 260];
    }

    const __nv_bfloat16* Kh  = g_Khi  + bh * Sv * Dv;
    const __nv_bfloat16* Kl  = g_Klo  + bh * Sv * Dv;
    const __nv_bfloat16* Vth = g_Vthi + bh * Dv * Sv;
    const __nv_bfloat16* Vtl = g_Vtlo + bh * Dv * Sv;

    float O[8][4] = {};
    float m0 = -1e30f, m1 = -1e30f, l0 = 0.f, l1 = 0.f;

    const int kbmax = 2 * (qt + 1);

    auto fill = [&](int buf, int kb) {
        const unsigned boff = sbase + buf * FBUF;
        #pragma unroll
        for (int it = 0; it < 8; ++it) {
            const int t = it >> 1;
            int e = tid + (it & 1) * 256;     // 0..511
            int r = e >> 3, c = e & 7;
            const __nv_bfloat16* g;
            if      (t == 0) g = Kh  + (size_t)(kb * 64 + r) * Dv + c * 8;
            else if (t == 1) g = Kl  + (size_t)(kb * 64 + r) * Dv + c * 8;
            else if (t == 2) g = Vth + (size_t)r * Sv + kb * 64 + c * 8;
            else             g = Vtl + (size_t)r * Sv + kb * 64 + c * 8;
            cp_async16(boff + t * TSZ + r * 144 + c * 16, g);
        }
    };

    fill(0, 0); CP_COMMIT();

    for (int kb = 0; kb < kbmax; ++kb) {
        const int buf = kb & 1;
        if (kb + 1 < kbmax) { fill(buf ^ 1, kb + 1); CP_COMMIT(); CP_WAIT(1); }
        else                { CP_WAIT(0); }
        __syncthreads();

        const unsigned tK_h = sbase + buf * FBUF;
        const unsigned tK_l = tK_h + TSZ;
        const unsigned tV_h = tK_h + 2 * TSZ;
        const unsigned tV_l = tK_h + 3 * TSZ;

        // S = Q @ K^T (16x64 per warp), 3-term split
        float sacc[8][4] = {};
        #pragma unroll
        for (int kc = 0; kc < 4; ++kc) {
            unsigned bhf[8][2], blf[8][2];
            #pragma unroll
            for (int ntp = 0; ntp < 4; ++ntp) {
                unsigned off = (unsigned)(ntp * 16 + f_row) * 144 + kc * 32 + f_cb;
                unsigned r4[4];
                LDSM_X4(r4, tK_h + off);
                bhf[ntp*2][0] = r4[0];  bhf[ntp*2][1] = r4[1];
                bhf[ntp*2+1][0] = r4[2]; bhf[ntp*2+1][1] = r4[3];
                LDSM_X4(r4, tK_l + off);
                blf[ntp*2][0] = r4[0];  blf[ntp*2][1] = r4[1];
                blf[ntp*2+1][0] = r4[2]; blf[ntp*2+1][1] = r4[3];
            }
            #pragma unroll
            for (int nt = 0; nt < 8; ++nt) {
                MMA_BF16(sacc[nt], qh[kc], bhf[nt]);
                MMA_BF16(sacc[nt], qh[kc], blf[nt]);
                MMA_BF16(sacc[nt], ql[kc], bhf[nt]);
            }
        }

        // causal mask (only the last two key blocks can cross the diagonal)
        if (kb >= kbmax - 2) {
            int r0 = q0 + wm + grp, r1 = r0 + 8;
            #pragma unroll
            for (int nt = 0; nt < 8; ++nt) {
                int c0 = kb * 64 + nt * 8 + 2 * ft;
                if (c0     > r0) sacc[nt][0] = -1e30f;
                if (c0 + 1 > r0) sacc[nt][1] = -1e30f;
                if (c0     > r1) sacc[nt][2] = -1e30f;
                if (c0 + 1 > r1) sacc[nt][3] = -1e30f;
            }
        }

        // online softmax in registers (rows grp / grp+8; quad holds full row)
        float mx0 = -1e30f, mx1 = -1e30f;
        #pragma unroll
        for (int nt = 0; nt < 8; ++nt) {
            mx0 = fmaxf(mx0, fmaxf(sacc[nt][0], sacc[nt][1]));
            mx1 = fmaxf(mx1, fmaxf(sacc[nt][2], sacc[nt][3]));
        }
        mx0 = fmaxf(mx0, __shfl_xor_sync(0xffffffffu, mx0, 1));
        mx0 = fmaxf(mx0, __shfl_xor_sync(0xffffffffu, mx0, 2));
        mx1 = fmaxf(mx1, __shfl_xor_sync(0xffffffffu, mx1, 1));
        mx1 = fmaxf(mx1, __shfl_xor_sync(0xffffffffu, mx1, 2));

        float mn0 = fmaxf(m0, mx0), mn1 = fmaxf(m1, mx1);
        float al0 = __expf(m0 - mn0), al1 = __expf(m1 - mn1);
        float ps0 = 0.f, ps1 = 0.f;
        #pragma unroll
        for (int nt = 0; nt < 8; ++nt) {
            sacc[nt][0] = __expf(sacc[nt][0] - mn0);
            sacc[nt][1] = __expf(sacc[nt][1] - mn0);
            sacc[nt][2] = __expf(sacc[nt][2] - mn1);
            sacc[nt][3] = __expf(sacc[nt][3] - mn1);
            ps0 += sacc[nt][0] + sacc[nt][1];
            ps1 += sacc[nt][2] + sacc[nt][3];
        }
        ps0 += __shfl_xor_sync(0xffffffffu, ps0, 1);
        ps0 += __shfl_xor_sync(0xffffffffu, ps0, 2);
        ps1 += __shfl_xor_sync(0xffffffffu, ps1, 1);
        ps1 += __shfl_xor_sync(0xffffffffu, ps1, 2);
        l0 = l0 * al0 + ps0;  l1 = l1 * al1 + ps1;
        m0 = mn0;             m1 = mn1;
        #pragma unroll
        for (int nt = 0; nt < 8; ++nt) {
            O[nt][0] *= al0;  O[nt][1] *= al0;
            O[nt][2] *= al1;  O[nt][3] *= al1;
        }

        // repack P (C layout -> A fragments, hi/lo split), lane-local
        unsigned ph[4][4], pl[4][4];
        #pragma unroll
        for (int kc = 0; kc < 4; ++kc) {
            split2(sacc[2*kc][0],   sacc[2*kc][1],   ph[kc][0], pl[kc][0]);
            split2(sacc[2*kc][2],   sacc[2*kc][3],   ph[kc][1], pl[kc][1]);
            split2(sacc[2*kc+1][0], sacc[2*kc+1][1], ph[kc][2], pl[kc][2]);
            split2(sacc[2*kc+1][2], sacc[2*kc+1][3], ph[kc][3], pl[kc][3]);
        }

        // O += P @ V  (V^T tile in smem is exactly B-fragment layout)
        #pragma unroll
        for (int kc = 0; kc < 4; ++kc) {
            unsigned vh[8][2], vl[8][2];
            #pragma unroll
            for (int ntp = 0; ntp < 4; ++ntp) {
                unsigned off = (unsigned)(ntp * 16 + f_row) * 144 + kc * 32 + f_cb;
                unsigned r4[4];
                LDSM_X4(r4, tV_h + off);
                vh[ntp*2][0] = r4[0];  vh[ntp*2][1] = r4[1];
                vh[ntp*2+1][0] = r4[2]; vh[ntp*2+1][1] = r4[3];
                LDSM_X4(r4, tV_l + off);
                vl[ntp*2][0] = r4[0];  vl[ntp*2][1] = r4[1];
                vl[ntp*2+1][0] = r4[2]; vl[ntp*2+1][1] = r4[3];
            }
            #pragma unroll
            for (int nt = 0; nt < 8; ++nt) {
                MMA_BF16(O[nt], ph[kc], vh[nt]);
                MMA_BF16(O[nt], ph[kc], vl[nt]);
                MMA_BF16(O[nt], pl[kc], vh[nt]);
            }
        }
        __syncthreads();
    }

    // normalize + write AO hi/lo split into [B,S,E]
    float inv0 = 1.f / l0, inv1 = 1.f / l1;
    int r0 = q0 + wm + grp, r1 = r0 + 8;
    #pragma unroll
    for (int nt = 0; nt < 8; ++nt) {
        int d = nt * 8 + 2 * ft;
        size_t off0 = ((size_t)b * Sv + r0) * Ev + h * 64 + d;
        size_t off1 = ((size_t)b * Sv + r1) * Ev + h * 64 + d;
        unsigned hw, lw;
        split2(O[nt][0] * inv0, O[nt][1] * inv0, hw, lw);
        *(unsigned*)(g_AOhi + off0) = hw;
        *(unsigned*)(g_AOlo + off0) = lw;
        split2(O[nt][2] * inv1, O[nt][3] * inv1, hw, lw);
        *(unsigned*)(g_AOhi + off1) = hw;
        *(unsigned*)(g_AOlo + off1) = lw;
    }
}

// ---------------------------------------------------------------------------
extern "C" void kernel_launch(void* const* d_in, const int* in_sizes, int n_in,
                              void* d_out, int out_size)
{
    const float* X  = (const float*)d_in[0];
    const float* Wq = (const float*)d_in[1];
    const float* Wk = (const float*)d_in[2];
    const float* Wv = (const float*)d_in[3];
    const float* Wo = (const float*)d_in[4];
    const float* bo = (const float*)d_in[5];
    float* out = (float*)d_out;

    const int mma_smem   = 2 * BUFSZ + 128;       // 82048
    const int flash_smem = 2 * FBUF + 128;        // 73856
    cudaFuncSetAttribute(qkv_mma, cudaFuncAttributeMaxDynamicSharedMemorySize, mma_smem);
    cudaFuncSetAttribute(out_mma, cudaFuncAttributeMaxDynamicSharedMemorySize, mma_smem);
    cudaFuncSetAttribute(flash_attn, cudaFuncAttributeMaxDynamicSharedMemorySize, flash_smem);

    split_x<<<4096, 256>>>(X, Mtot * Ev);
    split_w<<<dim3(32, 32, 4), 256>>>(Wq, Wk, Wv, Wo);

    qkv_mma<<<dim3(8, 256, 3), 256, mma_smem>>>();

    flash_attn<<<dim3(4, Hv, Bv), 256, flash_smem>>>();

    out_mma<<<dim3(8, 256), 256, mma_smem>>>(bo, out);
}